// round 1
// baseline (speedup 1.0000x reference)
#include <cuda_runtime.h>

#define HID 128
#define BLOCK 256

// SMEM float layout
//  sW2 : [0, 16384)          W2[k][j], k-major (row-major as given: (128,128))
//  sW1 : [16384, 17024)      W1[i][j]  (5,128)
//  sW3 : [17024, 17408)      W3[j][t]  (128,3)
//  sb1 : [17408, 17536)
//  sb2 : [17536, 17664)
//  sb3 : [17664, 17668)
#define SMEM_FLOATS (16384 + 640 + 384 + 128 + 128 + 4)

__global__ __launch_bounds__(BLOCK, 1)
void dyn_reward_kernel(const float* __restrict__ s, const float* __restrict__ a,
                       const float* __restrict__ W1, const float* __restrict__ b1,
                       const float* __restrict__ W2, const float* __restrict__ b2,
                       const float* __restrict__ W3, const float* __restrict__ b3,
                       float* __restrict__ out, int B)
{
    extern __shared__ float sm[];
    float* sW2 = sm;
    float* sW1 = sm + 16384;
    float* sW3 = sW1 + 640;   // only 5*128=640 used for W1; W3 uses 384
    float* sb1 = sW3 + 384;
    float* sb2 = sb1 + 128;
    float* sb3 = sb2 + 128;

    const int tid = threadIdx.x;

    // Cooperative stage of weights into SMEM (all L2-hot after first wave)
    {
        const float4* W2v = (const float4*)W2;
        float4* sW2v = (float4*)sW2;
        #pragma unroll
        for (int i = tid; i < 16384 / 4; i += BLOCK) sW2v[i] = W2v[i];
        for (int i = tid; i < 640; i += BLOCK) sW1[i] = W1[i];
        for (int i = tid; i < 384; i += BLOCK) sW3[i] = W3[i];
        if (tid < 128) { sb1[tid] = b1[tid]; sb2[tid] = b2[tid]; }
        if (tid < 3)   { sb3[tid] = b3[tid]; }
    }
    __syncthreads();

    const int row = blockIdx.x * BLOCK + tid;
    if (row >= B) return;

    // Inputs
    const float x0 = s[row * 3 + 0];
    const float x1 = s[row * 3 + 1];
    const float x2 = s[row * 3 + 2];
    const float x3 = a[row * 2 + 0];
    const float x4 = a[row * 2 + 1];

    // ---------------- Layer 1: h1 = relu([x]*W1 + b1), kept in registers ----
    float h1[HID];
    #pragma unroll
    for (int j4 = 0; j4 < HID; j4 += 4) {
        float4 w0 = *(const float4*)(sW1 + 0 * 128 + j4);
        float4 w1 = *(const float4*)(sW1 + 1 * 128 + j4);
        float4 w2 = *(const float4*)(sW1 + 2 * 128 + j4);
        float4 w3 = *(const float4*)(sW1 + 3 * 128 + j4);
        float4 w4 = *(const float4*)(sW1 + 4 * 128 + j4);
        float4 bb = *(const float4*)(sb1 + j4);
        float v0 = bb.x + x0 * w0.x + x1 * w1.x + x2 * w2.x + x3 * w3.x + x4 * w4.x;
        float v1 = bb.y + x0 * w0.y + x1 * w1.y + x2 * w2.y + x3 * w3.y + x4 * w4.y;
        float v2 = bb.z + x0 * w0.z + x1 * w1.z + x2 * w2.z + x3 * w3.z + x4 * w4.z;
        float v3 = bb.w + x0 * w0.w + x1 * w1.w + x2 * w2.w + x3 * w3.w + x4 * w4.w;
        h1[j4 + 0] = fmaxf(v0, 0.0f);
        h1[j4 + 1] = fmaxf(v1, 0.0f);
        h1[j4 + 2] = fmaxf(v2, 0.0f);
        h1[j4 + 3] = fmaxf(v3, 0.0f);
    }

    // ---------------- Layer 2 + fused Layer 3 -------------------------------
    float o0 = sb3[0], o1 = sb3[1], o2 = sb3[2];

    #pragma unroll 1
    for (int jb = 0; jb < HID / 4; ++jb) {
        float4 acc = *(const float4*)(sb2 + jb * 4);
        const float* w2p = sW2 + jb * 4;
        #pragma unroll
        for (int k = 0; k < HID; ++k) {
            const float4 w = *(const float4*)(w2p + k * 128);
            const float hk = h1[k];
            acc.x = fmaf(hk, w.x, acc.x);
            acc.y = fmaf(hk, w.y, acc.y);
            acc.z = fmaf(hk, w.z, acc.z);
            acc.w = fmaf(hk, w.w, acc.w);
        }
        const float h20 = fmaxf(acc.x, 0.0f);
        const float h21 = fmaxf(acc.y, 0.0f);
        const float h22 = fmaxf(acc.z, 0.0f);
        const float h23 = fmaxf(acc.w, 0.0f);
        const float* w3p = sW3 + jb * 4 * 3;
        o0 = fmaf(h20, w3p[0], fmaf(h21, w3p[3], fmaf(h22, w3p[6], fmaf(h23, w3p[9],  o0))));
        o1 = fmaf(h20, w3p[1], fmaf(h21, w3p[4], fmaf(h22, w3p[7], fmaf(h23, w3p[10], o1))));
        o2 = fmaf(h20, w3p[2], fmaf(h21, w3p[5], fmaf(h22, w3p[8], fmaf(h23, w3p[11], o2))));
    }

    out[row * 3 + 0] = o0;
    out[row * 3 + 1] = o1;
    out[row * 3 + 2] = o2;

    // ---------------- Reward -------------------------------------------------
    // gauss mixture: 6 obstacles at (0,0),(0,.2),(0,.4),(0,.6),(0,.8),(-.8,-.8)
    const float INV2VAR = 14.2857142857f;          // 1/(2*0.035)
    const float GC      = 454.728409f;             // 100/(2*pi*0.035)
    const float BEXP    = 555.5555556f;            // 0.5/(0.03^2)
    const float BC      = 132.9807601f;            // 10/(0.03*sqrt(2*pi))

    float g = 0.0f;
    {
        float dx, dy;
        dx = x0 - 0.0f;  dy = x1 - 0.0f;  g += __expf(-(dx * dx + dy * dy) * INV2VAR);
        dx = x0 - 0.0f;  dy = x1 - 0.2f;  g += __expf(-(dx * dx + dy * dy) * INV2VAR);
        dx = x0 - 0.0f;  dy = x1 - 0.4f;  g += __expf(-(dx * dx + dy * dy) * INV2VAR);
        dx = x0 - 0.0f;  dy = x1 - 0.6f;  g += __expf(-(dx * dx + dy * dy) * INV2VAR);
        dx = x0 - 0.0f;  dy = x1 - 0.8f;  g += __expf(-(dx * dx + dy * dy) * INV2VAR);
        dx = x0 + 0.8f;  dy = x1 + 0.8f;  g += __expf(-(dx * dx + dy * dy) * INV2VAR);
    }
    const float gauss = GC * g;

    const float dq0 = x0 - x3;
    const float dq1 = x1 - x4;
    const float quad = 30.0f * (dq0 * dq0 + dq1 * dq1);

    float bsum = 0.0f;
    {
        float t;
        t = x0 + 1.5f; bsum += __expf(-t * t * BEXP);
        t = x0 - 1.5f; bsum += __expf(-t * t * BEXP);
        t = x1 - 1.0f; bsum += __expf(-t * t * BEXP);
        t = x1 + 1.0f; bsum += __expf(-t * t * BEXP);
    }
    const float bound = BC * bsum;

    out[(size_t)B * 3 + row] = -(quad + gauss + bound);
}

extern "C" void kernel_launch(void* const* d_in, const int* in_sizes, int n_in,
                              void* d_out, int out_size) {
    const float* s  = (const float*)d_in[0];
    const float* a  = (const float*)d_in[1];
    const float* W1 = (const float*)d_in[2];
    const float* b1 = (const float*)d_in[3];
    const float* W2 = (const float*)d_in[4];
    const float* b2 = (const float*)d_in[5];
    const float* W3 = (const float*)d_in[6];
    const float* b3 = (const float*)d_in[7];
    float* out = (float*)d_out;

    const int B = in_sizes[0] / 3;
    const size_t smem = SMEM_FLOATS * sizeof(float);
    cudaFuncSetAttribute(dyn_reward_kernel,
                         cudaFuncAttributeMaxDynamicSharedMemorySize, (int)smem);
    const int grid = (B + BLOCK - 1) / BLOCK;
    dyn_reward_kernel<<<grid, BLOCK, smem>>>(s, a, W1, b1, W2, b2, W3, b3, out, B);
}

// round 3
// speedup vs baseline: 2.3607x; 2.3607x over previous
#include <cuda_runtime.h>
#include <cuda_bf16.h>
#include <cstdint>

#define TILE    128
#define THREADS 256
#define GRID    148
#define STRIDE_E 136            // bf16 elems per padded row
#define STRIDE_B 272            // bytes per padded row (16B aligned, conflict-free for LDSM)

// SMEM byte offsets
#define W2HI_OFF 0              // W2 [k][n] hi  128x136 bf16 = 34816B
#define W2LO_OFF 34816
#define H1HI_OFF 69632          // h1 [m][k] hi
#define H1LO_OFF 104448
#define SMALL_OFF 139264        // floats: sW1 640 | sb1 128 | sb2 128 | sW3T 384 | sb3 4
#define SMEM_TOTAL (139264 + 5136)

__device__ __forceinline__ uint32_t smem_u32(const void* p) {
    uint32_t a;
    asm("{ .reg .u64 t; cvta.to.shared.u64 t, %1; cvt.u32.u64 %0, t; }"
        : "=r"(a) : "l"(p));
    return a;
}

__device__ __forceinline__ void ldsm4(uint32_t* r, uint32_t addr) {
    asm volatile("ldmatrix.sync.aligned.m8n8.x4.shared.b16 {%0,%1,%2,%3}, [%4];"
                 : "=r"(r[0]), "=r"(r[1]), "=r"(r[2]), "=r"(r[3]) : "r"(addr));
}
__device__ __forceinline__ void ldsm4t(uint32_t* r, uint32_t addr) {
    asm volatile("ldmatrix.sync.aligned.m8n8.x4.trans.shared.b16 {%0,%1,%2,%3}, [%4];"
                 : "=r"(r[0]), "=r"(r[1]), "=r"(r[2]), "=r"(r[3]) : "r"(addr));
}
__device__ __forceinline__ void mma16816(float* d, const uint32_t* a,
                                         uint32_t b0, uint32_t b1) {
    asm volatile("mma.sync.aligned.m16n8k16.row.col.f32.bf16.bf16.f32 "
                 "{%0,%1,%2,%3}, {%4,%5,%6,%7}, {%8,%9}, {%0,%1,%2,%3};"
                 : "+f"(d[0]), "+f"(d[1]), "+f"(d[2]), "+f"(d[3])
                 : "r"(a[0]), "r"(a[1]), "r"(a[2]), "r"(a[3]), "r"(b0), "r"(b1));
}

__global__ __launch_bounds__(THREADS, 1)
void dyn_reward_hmma_kernel(const float* __restrict__ s, const float* __restrict__ a,
                            const float* __restrict__ W1, const float* __restrict__ b1,
                            const float* __restrict__ W2, const float* __restrict__ b2,
                            const float* __restrict__ W3, const float* __restrict__ b3,
                            float* __restrict__ out, int B, int ntile) {
    extern __shared__ char sm[];
    const uint32_t smbase = smem_u32(sm);

    float* smallf = (float*)(sm + SMALL_OFF);
    float* sW1  = smallf;           // 640
    float* sb1  = sW1 + 640;        // 128
    float* sb2  = sb1 + 128;        // 128
    float* sW3T = sb2 + 128;        // 384 : sW3T[t*128+j] = W3[j][t]
    float* sb3  = sW3T + 384;       // 4

    const int tid = threadIdx.x;
    const int w = tid >> 5, lane = tid & 31;
    const int bid = blockIdx.x;

    // ---------------- one-time staging ----------------
    for (int i = tid; i < 640; i += THREADS) sW1[i] = W1[i];
    for (int i = tid; i < 384; i += THREADS) {
        int tt = i >> 7, j = i & 127;
        sW3T[i] = W3[j * 3 + tt];
    }
    if (tid < 128) { sb1[tid] = b1[tid]; sb2[tid] = b2[tid]; }
    if (tid < 3)   { sb3[tid] = b3[tid]; }
    {
        __nv_bfloat16* w2h = (__nv_bfloat16*)(sm + W2HI_OFF);
        __nv_bfloat16* w2l = (__nv_bfloat16*)(sm + W2LO_OFF);
        for (int idx = tid; idx < 16384; idx += THREADS) {
            int k = idx >> 7, n = idx & 127;
            float wv = W2[idx];
            __nv_bfloat16 hi = __float2bfloat16_rn(wv);
            __nv_bfloat16 lo = __float2bfloat16_rn(wv - __bfloat162float(hi));
            w2h[k * STRIDE_E + n] = hi;
            w2l[k * STRIDE_E + n] = lo;
        }
    }
    __syncthreads();

    // ldmatrix lane-address offsets (canonical x4 recipe)
    const uint32_t a_off = (uint32_t)((w * 16 + (lane & 15)) * STRIDE_B + ((lane >> 4) << 4));
    const uint32_t b_off = (uint32_t)((lane & 15) * STRIDE_B + ((lane >> 4) << 4));

    const int nt = (ntile - bid + GRID - 1) / GRID;

    for (int it = 0; it < nt; ++it) {
        const int R0 = (bid + it * GRID) * TILE;

        // ---------------- layer 1: h1 = relu(xW1+b1), split hi/lo ----------------
        {
            const int row = tid & 127;
            const int half = tid >> 7;
            const int R = R0 + row;
            const float x0 = s[(size_t)R * 3 + 0];
            const float x1 = s[(size_t)R * 3 + 1];
            const float x2 = s[(size_t)R * 3 + 2];
            const float x3 = a[(size_t)R * 2 + 0];
            const float x4 = a[(size_t)R * 2 + 1];
            char* hiP = sm + H1HI_OFF;
            char* loP = sm + H1LO_OFF;
            #pragma unroll
            for (int g = 0; g < 8; ++g) {
                const int j = half * 64 + g * 8;
                float v[8];
                #pragma unroll
                for (int u = 0; u < 8; u += 4) {
                    float4 wb = *(const float4*)(sb1 + j + u);
                    float4 w0 = *(const float4*)(sW1 + 0 * 128 + j + u);
                    float4 w1 = *(const float4*)(sW1 + 1 * 128 + j + u);
                    float4 w2 = *(const float4*)(sW1 + 2 * 128 + j + u);
                    float4 w3 = *(const float4*)(sW1 + 3 * 128 + j + u);
                    float4 w4 = *(const float4*)(sW1 + 4 * 128 + j + u);
                    v[u+0] = fmaxf(wb.x + x0*w0.x + x1*w1.x + x2*w2.x + x3*w3.x + x4*w4.x, 0.0f);
                    v[u+1] = fmaxf(wb.y + x0*w0.y + x1*w1.y + x2*w2.y + x3*w3.y + x4*w4.y, 0.0f);
                    v[u+2] = fmaxf(wb.z + x0*w0.z + x1*w1.z + x2*w2.z + x3*w3.z + x4*w4.z, 0.0f);
                    v[u+3] = fmaxf(wb.w + x0*w0.w + x1*w1.w + x2*w2.w + x3*w3.w + x4*w4.w, 0.0f);
                }
                uint32_t hw[4], lw[4];
                #pragma unroll
                for (int u = 0; u < 8; u += 2) {
                    __nv_bfloat16 h0 = __float2bfloat16_rn(v[u]);
                    __nv_bfloat16 h1_ = __float2bfloat16_rn(v[u+1]);
                    float r0 = v[u]   - __bfloat162float(h0);
                    float r1 = v[u+1] - __bfloat162float(h1_);
                    __nv_bfloat162 hp = __halves2bfloat162(h0, h1_);
                    __nv_bfloat162 lp = __halves2bfloat162(__float2bfloat16_rn(r0),
                                                           __float2bfloat16_rn(r1));
                    hw[u>>1] = *reinterpret_cast<uint32_t*>(&hp);
                    lw[u>>1] = *reinterpret_cast<uint32_t*>(&lp);
                }
                const uint32_t off = (uint32_t)(row * STRIDE_B + j * 2);
                *reinterpret_cast<uint4*>(hiP + off) = make_uint4(hw[0], hw[1], hw[2], hw[3]);
                *reinterpret_cast<uint4*>(loP + off) = make_uint4(lw[0], lw[1], lw[2], lw[3]);
            }
        }
        __syncthreads();

        // ---------------- layer 2: 3-pass bf16x3 HMMA -------------------
        float acc[64];
        #pragma unroll
        for (int z = 0; z < 64; ++z) acc[z] = 0.0f;

        #pragma unroll
        for (int pass = 0; pass < 3; ++pass) {
            const uint32_t Ab = smbase + (pass == 2 ? H1LO_OFF : H1HI_OFF) + a_off;
            const uint32_t Bb = smbase + (pass == 1 ? W2LO_OFF : W2HI_OFF) + b_off;
            uint32_t af[8][4];
            #pragma unroll
            for (int ks = 0; ks < 8; ++ks) ldsm4(af[ks], Ab + ks * 32);
            #pragma unroll
            for (int p = 0; p < 8; ++p) {
                #pragma unroll
                for (int ks = 0; ks < 8; ++ks) {
                    uint32_t bfr[4];
                    ldsm4t(bfr, Bb + (uint32_t)(ks * 16 * STRIDE_B + p * 32));
                    mma16816(acc + (p * 2 + 0) * 4, af[ks], bfr[0], bfr[1]);
                    mma16816(acc + (p * 2 + 1) * 4, af[ks], bfr[2], bfr[3]);
                }
            }
        }
        __syncthreads();   // all LDSM done -> h1 SMEM reusable next tile

        // ---------------- layer 3 + reward, register epilogue -----------
        float p0 = 0, p1 = 0, p2 = 0, q0 = 0, q1 = 0, q2 = 0;
        #pragma unroll
        for (int ntl = 0; ntl < 16; ++ntl) {
            const int c0 = ntl * 8 + (lane & 3) * 2;
            const int c1 = c0 + 1;
            const float b20 = sb2[c0], b21 = sb2[c1];
            const float h00 = fmaxf(acc[ntl*4+0] + b20, 0.0f);
            const float h01 = fmaxf(acc[ntl*4+1] + b21, 0.0f);
            const float h10 = fmaxf(acc[ntl*4+2] + b20, 0.0f);
            const float h11 = fmaxf(acc[ntl*4+3] + b21, 0.0f);
            const float wa0 = sW3T[c0],        wa1 = sW3T[c1];
            const float wb0 = sW3T[128 + c0],  wb1 = sW3T[128 + c1];
            const float wc0 = sW3T[256 + c0],  wc1 = sW3T[256 + c1];
            p0 = fmaf(h00, wa0, fmaf(h01, wa1, p0));
            p1 = fmaf(h00, wb0, fmaf(h01, wb1, p1));
            p2 = fmaf(h00, wc0, fmaf(h01, wc1, p2));
            q0 = fmaf(h10, wa0, fmaf(h11, wa1, q0));
            q1 = fmaf(h10, wb0, fmaf(h11, wb1, q1));
            q2 = fmaf(h10, wc0, fmaf(h11, wc1, q2));
        }
        #pragma unroll
        for (int d = 1; d < 4; d <<= 1) {
            p0 += __shfl_xor_sync(0xFFFFFFFFu, p0, d);
            p1 += __shfl_xor_sync(0xFFFFFFFFu, p1, d);
            p2 += __shfl_xor_sync(0xFFFFFFFFu, p2, d);
            q0 += __shfl_xor_sync(0xFFFFFFFFu, q0, d);
            q1 += __shfl_xor_sync(0xFFFFFFFFu, q1, d);
            q2 += __shfl_xor_sync(0xFFFFFFFFu, q2, d);
        }
        if ((lane & 3) == 0) {
            const int rbase = R0 + w * 16 + (lane >> 2);
            const float oo[2][3] = { {p0, p1, p2}, {q0, q1, q2} };
            #pragma unroll
            for (int rr = 0; rr < 2; ++rr) {
                const int R = rbase + rr * 8;
                out[(size_t)R * 3 + 0] = oo[rr][0] + sb3[0];
                out[(size_t)R * 3 + 1] = oo[rr][1] + sb3[1];
                out[(size_t)R * 3 + 2] = oo[rr][2] + sb3[2];
                const float x0 = s[(size_t)R * 3 + 0];
                const float x1 = s[(size_t)R * 3 + 1];
                const float x3 = a[(size_t)R * 2 + 0];
                const float x4 = a[(size_t)R * 2 + 1];
                const float INV2VAR = 14.2857142857f;
                const float GC      = 454.728409f;
                const float BEXP    = 555.5555556f;
                const float BC      = 132.9807601f;
                float g = 0.0f, dx, dy, t;
                dx = x0;        dy = x1;        g += __expf(-(dx*dx + dy*dy) * INV2VAR);
                dx = x0;        dy = x1 - 0.2f; g += __expf(-(dx*dx + dy*dy) * INV2VAR);
                dx = x0;        dy = x1 - 0.4f; g += __expf(-(dx*dx + dy*dy) * INV2VAR);
                dx = x0;        dy = x1 - 0.6f; g += __expf(-(dx*dx + dy*dy) * INV2VAR);
                dx = x0;        dy = x1 - 0.8f; g += __expf(-(dx*dx + dy*dy) * INV2VAR);
                dx = x0 + 0.8f; dy = x1 + 0.8f; g += __expf(-(dx*dx + dy*dy) * INV2VAR);
                const float dq0 = x0 - x3, dq1 = x1 - x4;
                const float quad = 30.0f * (dq0 * dq0 + dq1 * dq1);
                float bs = 0.0f;
                t = x0 + 1.5f; bs += __expf(-t * t * BEXP);
                t = x0 - 1.5f; bs += __expf(-t * t * BEXP);
                t = x1 - 1.0f; bs += __expf(-t * t * BEXP);
                t = x1 + 1.0f; bs += __expf(-t * t * BEXP);
                out[(size_t)B * 3 + R] = -(quad + GC * g + BC * bs);
            }
        }
    }
}

extern "C" void kernel_launch(void* const* d_in, const int* in_sizes, int n_in,
                              void* d_out, int out_size) {
    const float* s  = (const float*)d_in[0];
    const float* a  = (const float*)d_in[1];
    const float* W1 = (const float*)d_in[2];
    const float* b1 = (const float*)d_in[3];
    const float* W2 = (const float*)d_in[4];
    const float* b2 = (const float*)d_in[5];
    const float* W3 = (const float*)d_in[6];
    const float* b3 = (const float*)d_in[7];
    float* out = (float*)d_out;

    const int B = in_sizes[0] / 3;
    const int ntile = B / TILE;       // 4096
    cudaFuncSetAttribute(dyn_reward_hmma_kernel,
                         cudaFuncAttributeMaxDynamicSharedMemorySize, SMEM_TOTAL);
    const int grid = (ntile < GRID) ? ntile : GRID;
    dyn_reward_hmma_kernel<<<grid, THREADS, SMEM_TOTAL>>>(s, a, W1, b1, W2, b2, W3, b3,
                                                          out, B, ntile);
}